// round 3
// baseline (speedup 1.0000x reference)
#include <cuda_runtime.h>
#include <cuda_bf16.h>

// LogSumExpPooling2D: x [8,256,256,64] f32 NHWC -> out [1,128,128,64]
// out[ho,wo,c] = (1/100) * log( sum_{n,dh,dw} exp(100 * x[n,2ho+dh,2wo+dw,c]) )
//
// R3: two warps per output pixel (split over dh) to halve per-thread register
// payload (v[8] instead of v[16]) -> occupancy 3->4+ CTAs/SM, and halve
// per-thread front-batched load count (MLP_p1 16->8) to cut cross-CTA
// L1tex-queue contention. dh-halves merged via smem (max,sum) partials.
//
// Block: 256 threads = 8 warps = 4 output pixels.
//   warp w: pixel p = w>>1, dh = w&1
//   lane:   dw = lane>>4, j = lane&15  (j = float4 channel group, 64ch = 16 f4)
// Per thread: 8 fully-coalesced LDG.128 over n=0..7. Intra-warp dw merge via
// shfl.xor(16); cross-warp dh merge via smem.

#define LSE_SCALE 100.0f
#define INV_SCALE 0.01f

__global__ __launch_bounds__(256)
void lse_pool_kernel(const float* __restrict__ x, float* __restrict__ out)
{
    __shared__ float4 m_sm[4][2][16];
    __shared__ float4 s_sm[4][2][16];

    const int warp = threadIdx.x >> 5;          // 0..7
    const int lane = threadIdx.x & 31;
    const int p    = warp >> 1;                  // 0..3 local pixel
    const int dh   = warp & 1;
    const int dw   = lane >> 4;                  // 0/1: even/odd w pixel
    const int j    = lane & 15;                  // float4 index in channels

    const int pixel = blockIdx.x * 4 + p;        // 0..16383
    const int wo    = pixel & 127;
    const int ho    = pixel >> 7;

    // float4 strides: w -> 16, h -> 4096, n -> 1048576
    const float4* __restrict__ xb = reinterpret_cast<const float4*>(x)
        + ((size_t)(2 * ho + dh) * 4096 + (size_t)(2 * wo + dw) * 16 + (size_t)j);

    // Front-batched: 8 independent LDG.128 per thread.
    float4 v[8];
#pragma unroll
    for (int n = 0; n < 8; ++n)
        v[n] = xb[(size_t)n * 1048576];

    // Per-channel max over the 8 local values.
    float4 m = v[0];
#pragma unroll
    for (int i = 1; i < 8; ++i) {
        m.x = fmaxf(m.x, v[i].x);
        m.y = fmaxf(m.y, v[i].y);
        m.z = fmaxf(m.z, v[i].z);
        m.w = fmaxf(m.w, v[i].w);
    }
    // Share max across the dw lane-pair.
    m.x = fmaxf(m.x, __shfl_xor_sync(0xffffffffu, m.x, 16));
    m.y = fmaxf(m.y, __shfl_xor_sync(0xffffffffu, m.y, 16));
    m.z = fmaxf(m.z, __shfl_xor_sync(0xffffffffu, m.z, 16));
    m.w = fmaxf(m.w, __shfl_xor_sync(0xffffffffu, m.w, 16));

    // Sum of exp(100*(v - m)).
    float4 s = make_float4(0.f, 0.f, 0.f, 0.f);
#pragma unroll
    for (int i = 0; i < 8; ++i) {
        s.x += __expf(LSE_SCALE * (v[i].x - m.x));
        s.y += __expf(LSE_SCALE * (v[i].y - m.y));
        s.z += __expf(LSE_SCALE * (v[i].z - m.z));
        s.w += __expf(LSE_SCALE * (v[i].w - m.w));
    }
    // Merge the two w-halves (shared max -> plain add).
    s.x += __shfl_xor_sync(0xffffffffu, s.x, 16);
    s.y += __shfl_xor_sync(0xffffffffu, s.y, 16);
    s.z += __shfl_xor_sync(0xffffffffu, s.z, 16);
    s.w += __shfl_xor_sync(0xffffffffu, s.w, 16);

    // Publish this dh-half's partial (m, s).
    if (dw == 0) {
        m_sm[p][dh][j] = m;
        s_sm[p][dh][j] = s;
    }
    __syncthreads();

    // dh==0 warps, dw==0 lanes: merge halves and write out.
    if (dh == 0 && dw == 0) {
        const float4 m1 = m_sm[p][1][j];
        const float4 s1 = s_sm[p][1][j];

        float4 M, o;
        M.x = fmaxf(m.x, m1.x);
        M.y = fmaxf(m.y, m1.y);
        M.z = fmaxf(m.z, m1.z);
        M.w = fmaxf(m.w, m1.w);

        float tx = s.x * __expf(LSE_SCALE * (m.x - M.x)) + s1.x * __expf(LSE_SCALE * (m1.x - M.x));
        float ty = s.y * __expf(LSE_SCALE * (m.y - M.y)) + s1.y * __expf(LSE_SCALE * (m1.y - M.y));
        float tz = s.z * __expf(LSE_SCALE * (m.z - M.z)) + s1.z * __expf(LSE_SCALE * (m1.z - M.z));
        float tw = s.w * __expf(LSE_SCALE * (m.w - M.w)) + s1.w * __expf(LSE_SCALE * (m1.w - M.w));

        o.x = M.x + __logf(tx) * INV_SCALE;
        o.y = M.y + __logf(ty) * INV_SCALE;
        o.z = M.z + __logf(tz) * INV_SCALE;
        o.w = M.w + __logf(tw) * INV_SCALE;

        reinterpret_cast<float4*>(out)[(size_t)pixel * 16 + j] = o;
    }
}

extern "C" void kernel_launch(void* const* d_in, const int* in_sizes, int n_in,
                              void* d_out, int out_size)
{
    const float* x = (const float*)d_in[0];
    float* out = (float*)d_out;
    // 16384 output pixels, 4 per block (2 warps each).
    lse_pool_kernel<<<4096, 256>>>(x, out);
}

// round 5
// speedup vs baseline: 1.1402x; 1.1402x over previous
#include <cuda_runtime.h>
#include <cuda_bf16.h>
#include <math_constants.h>

// LogSumExpPooling2D: x [8,256,256,64] f32 NHWC -> out [1,128,128,64]
// out[ho,wo,c] = (1/100) * log( sum_{n,dh,dw} exp(100 * x[n,2ho+dh,2wo+dw,c]) )
//
// R4: R2 structure (1 warp/pixel, lanes split dw, 16 coalesced LDG.128/thread)
// but the 16 loads are processed as 4 chunks of 4 with a 2-deep register
// pipeline + online rescaled LSE. Loads interleave with compute (no bulk
// load->compute phase oscillation) and payload registers drop 64 -> ~36,
// lifting occupancy without R3's per-byte instruction bloat.

#define LSE_SCALE 100.0f
#define INV_SCALE 0.01f

__global__ __launch_bounds__(256)
void lse_pool_kernel(const float* __restrict__ x, float* __restrict__ out)
{
    const int warp = (blockIdx.x * 256 + threadIdx.x) >> 5;  // 0..16383
    const int lane = threadIdx.x & 31;
    const int wo   = warp & 127;
    const int ho   = warp >> 7;
    const int dw   = lane >> 4;   // 0: even w pixel, 1: odd w pixel
    const int j    = lane & 15;   // float4 index within 64 channels

    // float4 strides: w -> 16, h -> 4096, n -> 1048576
    const float4* __restrict__ xb = reinterpret_cast<const float4*>(x)
        + ((size_t)(2 * ho) * 4096 + (size_t)(2 * wo + dw) * 16 + (size_t)j);

    // value index i in [0,16): n = i>>1, dh = i&1
    float4 v[2][4];

#define LOAD_CHUNK(buf, c)                                                    \
    {                                                                         \
        _Pragma("unroll")                                                     \
        for (int k = 0; k < 4; ++k) {                                         \
            const int i = (c) * 4 + k;                                        \
            v[buf][k] = xb[(size_t)(i >> 1) * 1048576 + (size_t)(i & 1) * 4096]; \
        }                                                                     \
    }

    LOAD_CHUNK(0, 0)

    float4 m = make_float4(-CUDART_INF_F, -CUDART_INF_F, -CUDART_INF_F, -CUDART_INF_F);
    float4 s = make_float4(0.f, 0.f, 0.f, 0.f);

#pragma unroll
    for (int c = 0; c < 4; ++c) {
        const int b = c & 1;
        if (c < 3) LOAD_CHUNK(b ^ 1, c + 1)

        // chunk max
        float4 mc = v[b][0];
#pragma unroll
        for (int k = 1; k < 4; ++k) {
            mc.x = fmaxf(mc.x, v[b][k].x);
            mc.y = fmaxf(mc.y, v[b][k].y);
            mc.z = fmaxf(mc.z, v[b][k].z);
            mc.w = fmaxf(mc.w, v[b][k].w);
        }
        float4 mn;
        mn.x = fmaxf(m.x, mc.x);
        mn.y = fmaxf(m.y, mc.y);
        mn.z = fmaxf(m.z, mc.z);
        mn.w = fmaxf(m.w, mc.w);

        // chunk sum of exp(K*(v - mn))
        float4 cs = make_float4(0.f, 0.f, 0.f, 0.f);
#pragma unroll
        for (int k = 0; k < 4; ++k) {
            cs.x += __expf(LSE_SCALE * (v[b][k].x - mn.x));
            cs.y += __expf(LSE_SCALE * (v[b][k].y - mn.y));
            cs.z += __expf(LSE_SCALE * (v[b][k].z - mn.z));
            cs.w += __expf(LSE_SCALE * (v[b][k].w - mn.w));
        }

        // rescale running sum and accumulate
        s.x = s.x * __expf(LSE_SCALE * (m.x - mn.x)) + cs.x;
        s.y = s.y * __expf(LSE_SCALE * (m.y - mn.y)) + cs.y;
        s.z = s.z * __expf(LSE_SCALE * (m.z - mn.z)) + cs.z;
        s.w = s.w * __expf(LSE_SCALE * (m.w - mn.w)) + cs.w;
        m = mn;
    }
#undef LOAD_CHUNK

    // Merge the two w-halves across the lane pair (rescaled add).
    {
        float mo, so, M;
#define MERGE(f)                                                              \
        mo = __shfl_xor_sync(0xffffffffu, m.f, 16);                           \
        so = __shfl_xor_sync(0xffffffffu, s.f, 16);                           \
        M  = fmaxf(m.f, mo);                                                  \
        s.f = s.f * __expf(LSE_SCALE * (m.f - M)) + so * __expf(LSE_SCALE * (mo - M)); \
        m.f = M;
        MERGE(x) MERGE(y) MERGE(z) MERGE(w)
#undef MERGE
    }

    if (dw == 0) {
        float4 o;
        o.x = m.x + __logf(s.x) * INV_SCALE;
        o.y = m.y + __logf(s.y) * INV_SCALE;
        o.z = m.z + __logf(s.z) * INV_SCALE;
        o.w = m.w + __logf(s.w) * INV_SCALE;
        reinterpret_cast<float4*>(out)[(size_t)(ho * 128 + wo) * 16 + j] = o;
    }
}

extern "C" void kernel_launch(void* const* d_in, const int* in_sizes, int n_in,
                              void* d_out, int out_size)
{
    const float* x = (const float*)d_in[0];
    float* out = (float*)d_out;
    // 128*128 output pixels, 1 warp each, 8 warps per 256-thread block.
    lse_pool_kernel<<<2048, 256>>>(x, out);
}

// round 6
// speedup vs baseline: 1.2465x; 1.0932x over previous
#include <cuda_runtime.h>
#include <cuda_bf16.h>

// LogSumExpPooling2D: x [8,256,256,64] f32 NHWC -> out [1,128,128,64]
// out[ho,wo,c] = (1/100) * log( sum_{n,dh,dw} exp(100 * x[n,2ho+dh,2wo+dw,c]) )
//
// R6: R2 structure (best so far: 1 warp/pixel, lanes split dw, 16 front-batched
// coalesced LDG.128/thread, shared-max shfl merge) with:
//  - fused exponent math: exp(100(v-m)) = ex2(K2*v - K2*m), one FFMA+EX2 per
//    value instead of FADD+FMUL+FMUL+EX2 (~30% fewer non-load instructions)
//  - log epilogue via lg2: out = m + log2(s) * (ln2/100)
//  - block=128 (same 24 warps/SM at 80 regs, but finer wave-tail quantum)

#define K2F       144.2695040889f     // 100 / ln(2)
#define LN2_D100  0.0069314718056f    // ln(2) / 100

__device__ __forceinline__ float ex2(float t) {
    float r;
    asm("ex2.approx.ftz.f32 %0, %1;" : "=f"(r) : "f"(t));
    return r;
}
__device__ __forceinline__ float lg2(float t) {
    float r;
    asm("lg2.approx.ftz.f32 %0, %1;" : "=f"(r) : "f"(t));
    return r;
}

__global__ __launch_bounds__(128)
void lse_pool_kernel(const float* __restrict__ x, float* __restrict__ out)
{
    const int warp = (blockIdx.x * 128 + threadIdx.x) >> 5;  // 0..16383
    const int lane = threadIdx.x & 31;
    const int wo   = warp & 127;
    const int ho   = warp >> 7;
    const int dw   = lane >> 4;   // 0: even w pixel, 1: odd w pixel
    const int j    = lane & 15;   // float4 index within 64 channels

    // float4 strides: w -> 16, h -> 4096, n -> 1048576
    const float4* __restrict__ xb = reinterpret_cast<const float4*>(x)
        + ((size_t)(2 * ho) * 4096 + (size_t)(2 * wo + dw) * 16 + (size_t)j);

    // Front-batched loads: 16 independent LDG.128 in flight per thread.
    float4 v[16];
#pragma unroll
    for (int n = 0; n < 8; ++n) {
#pragma unroll
        for (int dh = 0; dh < 2; ++dh) {
            v[n * 2 + dh] = xb[(size_t)n * 1048576 + (size_t)dh * 4096];
        }
    }

    // Per-channel max over the 16 local values.
    float4 m = v[0];
#pragma unroll
    for (int i = 1; i < 16; ++i) {
        m.x = fmaxf(m.x, v[i].x);
        m.y = fmaxf(m.y, v[i].y);
        m.z = fmaxf(m.z, v[i].z);
        m.w = fmaxf(m.w, v[i].w);
    }
    // Share max across the dw lane-pair so both halves use the same reference.
    m.x = fmaxf(m.x, __shfl_xor_sync(0xffffffffu, m.x, 16));
    m.y = fmaxf(m.y, __shfl_xor_sync(0xffffffffu, m.y, 16));
    m.z = fmaxf(m.z, __shfl_xor_sync(0xffffffffu, m.z, 16));
    m.w = fmaxf(m.w, __shfl_xor_sync(0xffffffffu, m.w, 16));

    // Negated base-2 shifted max: exp(100(v-m)) = ex2(K2*v + nk)
    float4 nk;
    nk.x = -K2F * m.x;
    nk.y = -K2F * m.y;
    nk.z = -K2F * m.z;
    nk.w = -K2F * m.w;

    // Sum of ex2(K2*v - K2*m): one FFMA + one EX2 per value.
    float4 s = make_float4(0.f, 0.f, 0.f, 0.f);
#pragma unroll
    for (int i = 0; i < 16; ++i) {
        s.x += ex2(fmaf(K2F, v[i].x, nk.x));
        s.y += ex2(fmaf(K2F, v[i].y, nk.y));
        s.z += ex2(fmaf(K2F, v[i].z, nk.z));
        s.w += ex2(fmaf(K2F, v[i].w, nk.w));
    }
    // Merge the two w-halves (same max -> plain add).
    s.x += __shfl_xor_sync(0xffffffffu, s.x, 16);
    s.y += __shfl_xor_sync(0xffffffffu, s.y, 16);
    s.z += __shfl_xor_sync(0xffffffffu, s.z, 16);
    s.w += __shfl_xor_sync(0xffffffffu, s.w, 16);

    if (dw == 0) {
        float4 o;
        o.x = fmaf(lg2(s.x), LN2_D100, m.x);
        o.y = fmaf(lg2(s.y), LN2_D100, m.y);
        o.z = fmaf(lg2(s.z), LN2_D100, m.z);
        o.w = fmaf(lg2(s.w), LN2_D100, m.w);
        reinterpret_cast<float4*>(out)[(size_t)(ho * 128 + wo) * 16 + j] = o;
    }
}

extern "C" void kernel_launch(void* const* d_in, const int* in_sizes, int n_in,
                              void* d_out, int out_size)
{
    const float* x = (const float*)d_in[0];
    float* out = (float*)d_out;
    // 16384 output pixels, 1 warp each, 4 warps per 128-thread block.
    lse_pool_kernel<<<4096, 128>>>(x, out);
}